// round 1
// baseline (speedup 1.0000x reference)
#include <cuda_runtime.h>

// Problem constants (from reference setup_inputs)
#define T_DIM 16
#define B_DIM 32
#define N_DIM 196
#define C_DIM 512
#define TB_STRIDE (B_DIM * N_DIM * C_DIM)   // elements per timestep = 3,211,264
#define SPIKES_ELEMS ((size_t)T_DIM * B_DIM * N_DIM * C_DIM)

// Block: 32 c-lanes (float2 each -> 64 c per block) x 32 n-groups.
// Each thread owns v-state for n = ny, ny+32, ..., (7 slots; last predicated).
// Each block covers ALL of N for its (b, c-tile) -> vpool reduction is
// block-local shared memory, no atomics, no cross-block communication.
__global__ __launch_bounds__(1024, 1)
void lif_dual_kernel(const float* __restrict__ x,
                     const float* __restrict__ decay,
                     float* __restrict__ spikes,
                     float* __restrict__ vpool) {
    const int cx    = threadIdx.x;   // 0..31
    const int ny    = threadIdx.y;   // 0..31
    const int ctile = blockIdx.x;    // 0..7   (64 c per tile)
    const int b     = blockIdx.y;    // 0..31
    const int c     = ctile * 64 + cx * 2;
    const int flat  = ny * 32 + cx;

    const float d = decay[0];
    const float inv_n = 1.0f / (float)N_DIM;

    __shared__ float red[32][64];

    // idx(t,b,n,c) = ((t*B + b)*N + n)*C + c
    const size_t base = ((size_t)b * N_DIM + ny) * C_DIM + c;
    const bool last_ok = (ny < (N_DIM - 6 * 32));   // ny < 4

    float2 v[7];
#pragma unroll
    for (int k = 0; k < 7; k++) v[k] = make_float2(0.0f, 0.0f);

    for (int t = 0; t < T_DIM; t++) {
        const size_t off = base + (size_t)t * TB_STRIDE;

        // Batch all loads first (maximize MLP; streaming hint: no reuse)
        float2 xv[7];
#pragma unroll
        for (int k = 0; k < 6; k++)
            xv[k] = __ldcs(reinterpret_cast<const float2*>(x + off + (size_t)k * 32 * C_DIM));
        if (last_ok)
            xv[6] = __ldcs(reinterpret_cast<const float2*>(x + off + (size_t)6 * 32 * C_DIM));

        float2 p = make_float2(0.0f, 0.0f);
#pragma unroll
        for (int k = 0; k < 6; k++) {
            float2 vv = v[k];
            vv.x = fmaf(d, vv.x, xv[k].x);
            vv.y = fmaf(d, vv.y, xv[k].y);
            p.x += vv.x;                       // vpool uses PRE-reset v
            p.y += vv.y;
            float sx = (vv.x >= 1.0f) ? 1.0f : 0.0f;
            float sy = (vv.y >= 1.0f) ? 1.0f : 0.0f;
            __stcs(reinterpret_cast<float2*>(spikes + off + (size_t)k * 32 * C_DIM),
                   make_float2(sx, sy));
            vv.x = (sx != 0.0f) ? 0.0f : vv.x; // hard reset to 0
            vv.y = (sy != 0.0f) ? 0.0f : vv.y;
            v[k] = vv;
        }
        if (last_ok) {
            float2 vv = v[6];
            vv.x = fmaf(d, vv.x, xv[6].x);
            vv.y = fmaf(d, vv.y, xv[6].y);
            p.x += vv.x;
            p.y += vv.y;
            float sx = (vv.x >= 1.0f) ? 1.0f : 0.0f;
            float sy = (vv.y >= 1.0f) ? 1.0f : 0.0f;
            __stcs(reinterpret_cast<float2*>(spikes + off + (size_t)6 * 32 * C_DIM),
                   make_float2(sx, sy));
            vv.x = (sx != 0.0f) ? 0.0f : vv.x;
            vv.y = (sy != 0.0f) ? 0.0f : vv.y;
            v[6] = vv;
        }

        // Block-local reduction over the 32 n-groups for this timestep.
        *reinterpret_cast<float2*>(&red[ny][2 * cx]) = p;
        __syncthreads();
        if (flat < 64) {
            float s = 0.0f;
#pragma unroll
            for (int j = 0; j < 32; j++) s += red[j][flat];
            vpool[((size_t)t * B_DIM + b) * C_DIM + ctile * 64 + flat] = s * inv_n;
        }
        __syncthreads();   // protect red[] before next timestep reuses it
    }
}

extern "C" void kernel_launch(void* const* d_in, const int* in_sizes, int n_in,
                              void* d_out, int out_size) {
    const float* x     = (const float*)d_in[0];
    const float* decay = (const float*)d_in[1];
    float* spikes = (float*)d_out;
    float* vpool  = (float*)d_out + SPIKES_ELEMS;

    dim3 grid(C_DIM / 64, B_DIM);   // 8 x 32 = 256 blocks
    dim3 block(32, 32);             // 1024 threads
    lif_dual_kernel<<<grid, block>>>(x, decay, spikes, vpool);
}

// round 2
// speedup vs baseline: 1.1147x; 1.1147x over previous
#include <cuda_runtime.h>

// Problem constants (from reference setup_inputs)
#define T_DIM 16
#define B_DIM 32
#define N_DIM 196
#define C_DIM 512
#define TB_STRIDE (B_DIM * N_DIM * C_DIM)   // elements per timestep
#define SPIKES_ELEMS ((size_t)T_DIM * B_DIM * N_DIM * C_DIM)

// 128 resident blocks (single wave on 148 SMs), each block processes TWO
// (b, ctile) work units sequentially. Block = 32 c-lanes (float2 -> 64 c)
// x 32 n-groups; each thread carries 7 v-states covering all N=196.
// Per timestep: batch 7 LDG.64 for t+1 BEFORE the barrier so the vpool
// reduction (64 threads, shared-mem) is fully hidden by in-flight loads.
// red[] is parity double-buffered -> ONE __syncthreads per timestep.
__global__ __launch_bounds__(1024, 1)
void lif_dual_kernel(const float* __restrict__ x,
                     const float* __restrict__ decay,
                     float* __restrict__ spikes,
                     float* __restrict__ vpool) {
    const int cx   = threadIdx.x;        // 0..31
    const int ny   = threadIdx.y;        // 0..31
    const int flat = ny * 32 + cx;

    const float d = decay[0];
    const float inv_n = 1.0f / (float)N_DIM;
    const bool last_ok = (ny < (N_DIM - 6 * 32));   // ny < 4

    __shared__ float red[2][32][64];

#pragma unroll 1
    for (int u = 0; u < 2; u++) {
        const int unit  = blockIdx.x + u * 128;   // 0..255
        const int ctile = unit & 7;
        const int b     = unit >> 3;

        // idx(t,b,n,c) = ((t*B + b)*N + n)*C + c ; this thread: n = ny + 32k
        const size_t base = ((size_t)b * N_DIM + ny) * C_DIM + ctile * 64 + cx * 2;

        float2 v[7];
#pragma unroll
        for (int k = 0; k < 7; k++) v[k] = make_float2(0.0f, 0.0f);

        // Prime the pipeline: loads for t=0
        float2 xv[7];
#pragma unroll
        for (int k = 0; k < 6; k++)
            xv[k] = __ldcs(reinterpret_cast<const float2*>(x + base + (size_t)k * 32 * C_DIM));
        if (last_ok)
            xv[6] = __ldcs(reinterpret_cast<const float2*>(x + base + (size_t)6 * 32 * C_DIM));

#pragma unroll 1
        for (int t = 0; t < T_DIM; t++) {
            const size_t off = base + (size_t)t * TB_STRIDE;
            const int par = t & 1;

            float2 p = make_float2(0.0f, 0.0f);
#pragma unroll
            for (int k = 0; k < 7; k++) {
                if (k == 6 && !last_ok) break;
                float2 vv = v[k];
                vv.x = fmaf(d, vv.x, xv[k].x);
                vv.y = fmaf(d, vv.y, xv[k].y);
                p.x += vv.x;                        // vpool uses PRE-reset v
                p.y += vv.y;
                float sx = (vv.x >= 1.0f) ? 1.0f : 0.0f;
                float sy = (vv.y >= 1.0f) ? 1.0f : 0.0f;
                __stcs(reinterpret_cast<float2*>(spikes + off + (size_t)k * 32 * C_DIM),
                       make_float2(sx, sy));
                vv.x = (sx != 0.0f) ? 0.0f : vv.x;  // hard reset
                vv.y = (sy != 0.0f) ? 0.0f : vv.y;
                v[k] = vv;
            }

            // Publish partial sums for this timestep
            *reinterpret_cast<float2*>(&red[par][ny][2 * cx]) = p;

            // Prefetch next timestep's inputs BEFORE the barrier so the
            // reduction below is hidden by memory latency.
            if (t < T_DIM - 1) {
                const size_t noff = off + (size_t)TB_STRIDE;
#pragma unroll
                for (int k = 0; k < 6; k++)
                    xv[k] = __ldcs(reinterpret_cast<const float2*>(x + noff + (size_t)k * 32 * C_DIM));
                if (last_ok)
                    xv[6] = __ldcs(reinterpret_cast<const float2*>(x + noff + (size_t)6 * 32 * C_DIM));
            }

            __syncthreads();

            // 64 threads reduce the 32 n-group partials for 64 c columns.
            // Safe with one barrier: next iteration writes the OTHER parity
            // buffer, and re-writing this one requires these reducer threads
            // to have passed the next barrier first.
            if (flat < 64) {
                float s = 0.0f;
#pragma unroll
                for (int j = 0; j < 32; j++) s += red[par][j][flat];
                vpool[((size_t)t * B_DIM + b) * C_DIM + ctile * 64 + flat] = s * inv_n;
            }
        }
        __syncthreads();   // unit boundary: red[] reuse + v reinit
    }
}

extern "C" void kernel_launch(void* const* d_in, const int* in_sizes, int n_in,
                              void* d_out, int out_size) {
    const float* x     = (const float*)d_in[0];
    const float* decay = (const float*)d_in[1];
    float* spikes = (float*)d_out;
    float* vpool  = (float*)d_out + SPIKES_ELEMS;

    dim3 grid(128, 1);    // single resident wave; 2 units per block
    dim3 block(32, 32);   // 1024 threads
    lif_dual_kernel<<<grid, block>>>(x, decay, spikes, vpool);
}